// round 10
// baseline (speedup 1.0000x reference)
#include <cuda_runtime.h>
#include <cstdint>

#define THREADS 256
#define HID 256
#define CHUNK 32

#define HS_FLOATS (64 * 256)            // activations
#define WS_FLOATS (2 * CHUNK * 256)     // weight double buffer
#define A0_FLOATS (64 * 64)             // PE input (63 padded to 64), reused as scratch
#define SMEM_BYTES ((HS_FLOATS + WS_FLOATS + A0_FLOATS) * 4)

__device__ __forceinline__ uint32_t sm_u32(const void* p) {
    return (uint32_t)__cvta_generic_to_shared(p);
}

__device__ __forceinline__ void cp_chunk(float* dst, const float* __restrict__ src, int tid) {
    // one CHUNK x 256 fp32 tile = 2048 float4 slots; 8 per thread
#pragma unroll
    for (int s = 0; s < 8; ++s) {
        int slot = tid + s * THREADS;
        asm volatile("cp.async.cg.shared.global [%0], [%1], 16;\n"
                     :: "r"(sm_u32(dst + slot * 4)), "l"(src + slot * 4) : "memory");
    }
}

// M=64 x N=256 register-tiled FMA over one 32-wide K chunk.
// Thread (tm = tid>>5, tn = tid&31) owns rows [tm*8, tm*8+8) and columns
// {tn*4..tn*4+3} U {128+tn*4..128+tn*4+3}  -> conflict-free LDS.128 on W rows,
// warp-uniform (broadcast) LDS.128 on A rows.
template<int AS>
__device__ __forceinline__ void mma_chunk(float (&acc)[8][8],
        const float* __restrict__ A, int kbase,
        const float* __restrict__ Wb, int r0, int n0a, int n0b) {
#pragma unroll
    for (int kk = 0; kk < CHUNK; kk += 4) {
        float4 a4[8];
#pragma unroll
        for (int i = 0; i < 8; ++i)
            a4[i] = *(const float4*)(A + (r0 + i) * AS + kbase + kk);
#pragma unroll
        for (int u = 0; u < 4; ++u) {
            const float* wr = Wb + (kk + u) * HID;
            float4 w0 = *(const float4*)(wr + n0a);
            float4 w1 = *(const float4*)(wr + n0b);
            float wv[8] = {w0.x, w0.y, w0.z, w0.w, w1.x, w1.y, w1.z, w1.w};
#pragma unroll
            for (int i = 0; i < 8; ++i) {
                float av = (u == 0) ? a4[i].x : (u == 1) ? a4[i].y
                         : (u == 2) ? a4[i].z : a4[i].w;
#pragma unroll
                for (int j = 0; j < 8; ++j)
                    acc[i][j] = fmaf(av, wv[j], acc[i][j]);
            }
        }
    }
}

__device__ __forceinline__ void finish_layer(float (&acc)[8][8],
        const float* __restrict__ bg, float* Out, int r0, int n0a, int n0b) {
    float4 bb0 = *(const float4*)(bg + n0a);
    float4 bb1 = *(const float4*)(bg + n0b);
    float bs[8] = {bb0.x, bb0.y, bb0.z, bb0.w, bb1.x, bb1.y, bb1.z, bb1.w};
    __syncthreads();  // all reads of the input activation buffer are done
#pragma unroll
    for (int i = 0; i < 8; ++i) {
        float4 v0, v1;
        v0.x = fmaxf(acc[i][0] + bs[0], 0.f);
        v0.y = fmaxf(acc[i][1] + bs[1], 0.f);
        v0.z = fmaxf(acc[i][2] + bs[2], 0.f);
        v0.w = fmaxf(acc[i][3] + bs[3], 0.f);
        v1.x = fmaxf(acc[i][4] + bs[4], 0.f);
        v1.y = fmaxf(acc[i][5] + bs[5], 0.f);
        v1.z = fmaxf(acc[i][6] + bs[6], 0.f);
        v1.w = fmaxf(acc[i][7] + bs[7], 0.f);
        *(float4*)(Out + (r0 + i) * HID + n0a) = v0;
        *(float4*)(Out + (r0 + i) * HID + n0b) = v1;
    }
    __syncthreads();
}

// 256x256 layer with cp.async double-buffered weight streaming, in-place on Hs.
__device__ __forceinline__ void big_layer(const float* __restrict__ Wg,
        const float* __restrict__ bg, float* Hs, float* Ws,
        int r0, int n0a, int n0b, int tid) {
    float acc[8][8];
#pragma unroll
    for (int i = 0; i < 8; ++i)
#pragma unroll
        for (int j = 0; j < 8; ++j) acc[i][j] = 0.f;

    cp_chunk(Ws, Wg, tid);
    asm volatile("cp.async.commit_group;\n" ::: "memory");
#pragma unroll 1
    for (int c = 0; c < 8; ++c) {
        asm volatile("cp.async.wait_group 0;\n" ::: "memory");
        __syncthreads();                          // chunk c visible to all threads
        if (c < 7) {
            cp_chunk(Ws + ((c + 1) & 1) * (CHUNK * HID),
                     Wg + (c + 1) * (CHUNK * HID), tid);
            asm volatile("cp.async.commit_group;\n" ::: "memory");
        }
        mma_chunk<HID>(acc, Hs, c * CHUNK, Ws + (c & 1) * (CHUNK * HID),
                       r0, n0a, n0b);
    }
    finish_layer(acc, bg, Hs, r0, n0a, n0b);
}

__global__ void __launch_bounds__(THREADS, 1)
nerf_fused_kernel(const float* __restrict__ origins,
                  const float* __restrict__ dirs,
                  const float* __restrict__ nearp,
                  const float* __restrict__ farp,
                  const float* __restrict__ W0, const float* __restrict__ b0,
                  const float* __restrict__ W1, const float* __restrict__ b1,
                  const float* __restrict__ W2, const float* __restrict__ b2,
                  const float* __restrict__ W3, const float* __restrict__ b3,
                  float* __restrict__ out) {
    extern __shared__ float sm[];
    float* Hs  = sm;                           // 64 x 256
    float* Ws  = sm + HS_FLOATS;               // 2 x 32 x 256
    float* A0s = sm + HS_FLOATS + WS_FLOATS;   // 64 x 64 (63 valid + zero pad)

    const int tid = threadIdx.x;
    const int ray = blockIdx.x;
    const int tm = tid >> 5, tn = tid & 31;
    const int r0 = tm * 8;
    const int n0a = tn * 4;
    const int n0b = 128 + tn * 4;

    const float nearv = *nearp, farv = *farp;
    const float step = (farv - nearv) * (1.0f / 64.0f);

    // ---- sample locations (faithful midpoint: b[s] + b[s+1]/2) into A0s cols 0..2
    if (tid < 192) {
        int s = tid / 3, d = tid % 3;
        float bs  = nearv + step * (float)s;
        float bs1 = nearv + step * (float)(s + 1);
        float mid = bs + 0.5f * bs1;
        A0s[s * 64 + d] = origins[ray * 3 + d] + mid * dirs[ray * 3 + d];
    }
    if (tid < 64) A0s[tid * 64 + 63] = 0.f;     // zero pad col 63
    __syncthreads();

    // ---- positional encoding: feature 3 + f*6 + j ; j<3 sin, j>=3 cos, dim = j%3
    for (int idx = tid; idx < 64 * 60; idx += THREADS) {
        int s = idx / 60, e = idx % 60;
        int f = e / 6, j = e % 6;
        float v = A0s[s * 64 + (j % 3)] * exp2f((float)f);
        A0s[s * 64 + 3 + e] = (j < 3) ? sinf(v) : cosf(v);
    }
    __syncthreads();

    // ---- layer 0: A0s[64x64] @ W0[63x256] (row 63 zero-filled)
    {
        float acc[8][8];
#pragma unroll
        for (int i = 0; i < 8; ++i)
#pragma unroll
            for (int j = 0; j < 8; ++j) acc[i][j] = 0.f;
#pragma unroll 1
        for (int c = 0; c < 2; ++c) {
            __syncthreads();
#pragma unroll
            for (int s = 0; s < 8; ++s) {
                int slot = tid + s * THREADS;           // 0..2047
                int row = slot >> 6, col4 = slot & 63;
                int gk = c * CHUNK + row;
                float4 v = make_float4(0.f, 0.f, 0.f, 0.f);
                if (gk < 63) v = *(const float4*)(W0 + gk * HID + col4 * 4);
                *(float4*)(Ws + slot * 4) = v;
            }
            __syncthreads();
            mma_chunk<64>(acc, A0s, c * CHUNK, Ws, r0, n0a, n0b);
        }
        finish_layer(acc, b0, Hs, r0, n0a, n0b);
    }

    // ---- layers 1, 2: 256x256, in-place on Hs
    big_layer(W1, b1, Hs, Ws, r0, n0a, n0b, tid);
    big_layer(W2, b2, Hs, Ws, r0, n0a, n0b, tid);

    // ---- layer 3: Hs[64x256] @ W3[256x4] + b3 -> A0s[0..255] (p*4+c)
    for (int i = tid; i < 1024; i += THREADS) Ws[i] = W3[i];
    __syncthreads();
    {
        int p = tid >> 2, cc = tid & 3;
        float a3 = b3[cc];
        const float* hrow = Hs + p * HID;
#pragma unroll 8
        for (int k = 0; k < HID; k += 4) {
            float4 h4 = *(const float4*)(hrow + k);
            a3 = fmaf(h4.x, Ws[(k + 0) * 4 + cc], a3);
            a3 = fmaf(h4.y, Ws[(k + 1) * 4 + cc], a3);
            a3 = fmaf(h4.z, Ws[(k + 2) * 4 + cc], a3);
            a3 = fmaf(h4.w, Ws[(k + 3) * 4 + cc], a3);
        }
        A0s[tid] = a3;
    }
    __syncthreads();

    // ---- alpha compositing
    float* out4s  = A0s;          // 256 floats
    float* alphas = A0s + 256;    // 64
    float* rgbs   = A0s + 320;    // 192
    if (tid < 64) {
        float sig = fmaxf(out4s[tid * 4 + 3], 0.f);
        float d0 = (nearv + step * (float)(tid + 1)) - (nearv + step * (float)tid);
        alphas[tid] = 1.f - expf(-sig * d0);
    }
    if (tid < 192) {
        int s = tid / 3, c = tid % 3;
        float x = out4s[s * 4 + c];
        rgbs[tid] = 1.f / (1.f + expf(-x));
    }
    __syncthreads();
    if (tid < 3) {
        float T = 1.f, accum = 0.f;
#pragma unroll 1
        for (int s = 0; s < 64; ++s) {
            float a = alphas[s];
            accum += T * a * rgbs[s * 3 + tid];
            T *= (1.f - a);
        }
        out[ray * 3 + tid] = accum;
    }
}

extern "C" void kernel_launch(void* const* d_in, const int* in_sizes, int n_in,
                              void* d_out, int out_size) {
    const float* origins = (const float*)d_in[0];
    const float* dirs    = (const float*)d_in[1];
    const float* nearp   = (const float*)d_in[2];
    const float* farp    = (const float*)d_in[3];
    const float* W0 = (const float*)d_in[4];
    const float* b0 = (const float*)d_in[5];
    const float* W1 = (const float*)d_in[6];
    const float* b1 = (const float*)d_in[7];
    const float* W2 = (const float*)d_in[8];
    const float* b2 = (const float*)d_in[9];
    const float* W3 = (const float*)d_in[10];
    const float* b3 = (const float*)d_in[11];
    float* out = (float*)d_out;

    cudaFuncSetAttribute(nerf_fused_kernel,
                         cudaFuncAttributeMaxDynamicSharedMemorySize, SMEM_BYTES);

    int rays = in_sizes[0] / 3;   // 2048
    nerf_fused_kernel<<<rays, THREADS, SMEM_BYTES>>>(
        origins, dirs, nearp, farp, W0, b0, W1, b1, W2, b2, W3, b3, out);
}

// round 14
// speedup vs baseline: 2.3543x; 2.3543x over previous
#include <cuda_runtime.h>
#include <cuda_bf16.h>
#include <cstdint>

// ---------------- gmem weight scratch: 18 chunk images ----------------
// Chunk image (40960 B): hi plane then lo plane; each plane = 256 n-rows x 80 B
// (64 B = 32 bf16 of k data + 16 B pad for bank-conflict-free LDS).
// Chunks: 0-1: W0 (K=64, row 63 zero), 2-9: W1, 10-17: W2.
#define CHUNK_BYTES 40960u
#define N_CHUNKS 18
__device__ __align__(16) unsigned char g_wscr[N_CHUNKS * CHUNK_BYTES];

// ---------------- SMEM layout (bytes) ----------------
// A planes: 128 rows x 132 u32-words (264 bf16, K=256 + 8 pad) per plane.
#define AW_BIG 132
#define AW_PE  36            // layer-0 A: K=64 (+8 pad) -> 36 words
#define SA_HI   0u
#define SA_LO   67584u
#define SB      135168u      // 2 x 40960 double buffer
#define SM_BIAS 217088u      // b0,b1,b2 : 3 x 1024 B
#define SM_W3   220160u      // 4096 B fp32
#define SM_B3   224256u      // 16 B
#define SM_RED  224288u      // out4s 2048 | alphas 512 | rgb 1536
#define SMEM_BYTES 228384u

__device__ __forceinline__ uint32_t sm_u32(const void* p) {
    return (uint32_t)__cvta_generic_to_shared(p);
}
__device__ __forceinline__ void cp16(uint32_t s, const void* g) {
    asm volatile("cp.async.cg.shared.global [%0], [%1], 16;" :: "r"(s), "l"(g) : "memory");
}
__device__ __forceinline__ void mma16816(float (&d)[4], const uint32_t (&a)[4],
                                         const uint32_t (&b)[2]) {
    asm volatile(
        "mma.sync.aligned.m16n8k16.row.col.f32.bf16.bf16.f32 "
        "{%0,%1,%2,%3}, {%4,%5,%6,%7}, {%8,%9}, {%0,%1,%2,%3};"
        : "+f"(d[0]), "+f"(d[1]), "+f"(d[2]), "+f"(d[3])
        : "r"(a[0]), "r"(a[1]), "r"(a[2]), "r"(a[3]), "r"(b[0]), "r"(b[1]));
}
__device__ __forceinline__ void split_pack(float a, float b, uint32_t& hi, uint32_t& lo) {
    __nv_bfloat16 ah = __float2bfloat16(a), bh = __float2bfloat16(b);
    hi = ((uint32_t)__bfloat16_as_ushort(bh) << 16) | (uint32_t)__bfloat16_as_ushort(ah);
    __nv_bfloat16 al = __float2bfloat16(a - __bfloat162float(ah));
    __nv_bfloat16 bl = __float2bfloat16(b - __bfloat162float(bh));
    lo = ((uint32_t)__bfloat16_as_ushort(bl) << 16) | (uint32_t)__bfloat16_as_ushort(al);
}
__device__ __forceinline__ float bf_lo(uint32_t u) {
    return __bfloat162float(__ushort_as_bfloat16((unsigned short)(u & 0xFFFFu)));
}
__device__ __forceinline__ float bf_hi(uint32_t u) {
    return __bfloat162float(__ushort_as_bfloat16((unsigned short)(u >> 16)));
}

// ---------------- prep: build padded hi/lo B = W^T chunk images ----------------
__global__ void nerf_prep_kernel(const float* __restrict__ W0, const float* __restrict__ W1,
                                 const float* __restrict__ W2) {
    const int t = blockIdx.x;                 // chunk id 0..17
    const float* W; int kbase; bool isW0 = false;
    if (t < 2)       { W = W0; kbase = t * 32; isW0 = true; }
    else if (t < 10) { W = W1; kbase = (t - 2) * 32; }
    else             { W = W2; kbase = (t - 10) * 32; }
    unsigned char* img = g_wscr + (size_t)t * CHUNK_BYTES;
    for (int idx = threadIdx.x; idx < 256 * 32; idx += blockDim.x) {
        int n = idx >> 5, k = idx & 31;
        int krow = kbase + k;
        float v = (isW0 && krow >= 63) ? 0.f : W[krow * 256 + n];
        __nv_bfloat16 h = __float2bfloat16(v);
        __nv_bfloat16 l = __float2bfloat16(v - __bfloat162float(h));
        uint32_t off = (uint32_t)n * 80u + (uint32_t)k * 2u;
        *(__nv_bfloat16*)(img + off) = h;
        *(__nv_bfloat16*)(img + 20480u + off) = l;
    }
}

// ---------------- one k32 chunk of a 128x256 GEMM, warp tile 32Mx128N ----------------
__device__ __forceinline__ void chunk_mma(float (&acc)[2][16][4],
        const uint32_t* __restrict__ Ah, const uint32_t* __restrict__ Al, int AW,
        const uint32_t* __restrict__ Bh, const uint32_t* __restrict__ Bl,
        int kb, int m0, int n0, int gq, int tig) {
#pragma unroll
    for (int ks = 0; ks < 32; ks += 16) {
        uint32_t ah[2][4], al[2][4];
        const int cw = ((kb + ks) >> 1) + tig;
#pragma unroll
        for (int i = 0; i < 2; ++i) {
            const int r = m0 + i * 16 + gq;
            ah[i][0] = Ah[r * AW + cw];           ah[i][1] = Ah[(r + 8) * AW + cw];
            ah[i][2] = Ah[r * AW + cw + 4];       ah[i][3] = Ah[(r + 8) * AW + cw + 4];
            al[i][0] = Al[r * AW + cw];           al[i][1] = Al[(r + 8) * AW + cw];
            al[i][2] = Al[r * AW + cw + 4];       al[i][3] = Al[(r + 8) * AW + cw + 4];
        }
#pragma unroll
        for (int h = 0; h < 2; ++h) {
            uint32_t bh[8][2], bl[8][2];
#pragma unroll
            for (int j = 0; j < 8; ++j) {
                const int n = n0 + (h * 8 + j) * 8 + gq;
                const int w = n * 20 + (ks >> 1) + tig;
                bh[j][0] = Bh[w]; bh[j][1] = Bh[w + 4];
                bl[j][0] = Bl[w]; bl[j][1] = Bl[w + 4];
            }
#pragma unroll
            for (int i = 0; i < 2; ++i)
#pragma unroll
                for (int j = 0; j < 8; ++j) {
                    mma16816(acc[i][h * 8 + j], ah[i], bh[j]);
                    mma16816(acc[i][h * 8 + j], ah[i], bl[j]);
                    mma16816(acc[i][h * 8 + j], al[i], bh[j]);
                }
        }
    }
}

// ---------------- main kernel ----------------
__global__ void __launch_bounds__(256, 1)
nerf_hmma_kernel(const float* __restrict__ origins, const float* __restrict__ dirs,
                 const float* __restrict__ nearp, const float* __restrict__ farp,
                 const float* __restrict__ b0g, const float* __restrict__ b1g,
                 const float* __restrict__ b2g, const float* __restrict__ W3g,
                 const float* __restrict__ b3g, float* __restrict__ out) {
    extern __shared__ unsigned char smraw[];
    const uint32_t smb = sm_u32(smraw);
    const int tid  = threadIdx.x;
    const int warp = tid >> 5, lane = tid & 31;
    const int gq = lane >> 2, tig = lane & 3;
    const int m0 = (warp & 3) * 32;
    const int n0 = (warp >> 2) * 128;

    uint32_t* AhW = (uint32_t*)(smraw + SA_HI);
    uint32_t* AlW = (uint32_t*)(smraw + SA_LO);

    // ---- stage chunk 0 + biases + W3 + b3 (one cp.async group) ----
    {
        const unsigned char* src = g_wscr;
        for (int s = tid; s < 2560; s += 256)
            cp16(smb + SB + (uint32_t)s * 16u, src + s * 16);
        if (tid < 64)        cp16(smb + SM_BIAS + (uint32_t)tid * 16u,          b0g + tid * 4);
        else if (tid < 128)  cp16(smb + SM_BIAS + 1024u + (uint32_t)(tid - 64) * 16u,  b1g + (tid - 64) * 4);
        else if (tid < 192)  cp16(smb + SM_BIAS + 2048u + (uint32_t)(tid - 128) * 16u, b2g + (tid - 128) * 4);
        cp16(smb + SM_W3 + (uint32_t)tid * 16u, W3g + tid * 4);
        if (tid == 0) cp16(smb + SM_B3, b3g);
        asm volatile("cp.async.commit_group;" ::: "memory");
    }

    const float nearv = *nearp;
    const float step = (*farp - nearv) * (1.0f / 64.0f);

    // ---- positional encoding -> A0 planes (stride AW_PE) ----
    if (tid < 128) {
        const int ray = blockIdx.x * 2 + (tid >> 6);
        const int s = tid & 63;
        const float mid = (nearv + step * (float)s) + 0.5f * (nearv + step * (float)(s + 1));
        float c0 = origins[ray * 3 + 0] + mid * dirs[ray * 3 + 0];
        float c1 = origins[ray * 3 + 1] + mid * dirs[ray * 3 + 1];
        float c2 = origins[ray * 3 + 2] + mid * dirs[ray * 3 + 2];
        float feat[64];
        feat[0] = c0; feat[1] = c1; feat[2] = c2;
#pragma unroll
        for (int f = 0; f < 10; ++f) {
            float m = (float)(1 << f);
            float s0, s1, s2, q0, q1, q2;
            sincosf(c0 * m, &s0, &q0);
            sincosf(c1 * m, &s1, &q1);
            sincosf(c2 * m, &s2, &q2);
            int b = 3 + f * 6;
            feat[b + 0] = s0; feat[b + 1] = s1; feat[b + 2] = s2;
            feat[b + 3] = q0; feat[b + 4] = q1; feat[b + 5] = q2;
        }
        feat[63] = 0.f;
#pragma unroll
        for (int j = 0; j < 32; ++j) {
            uint32_t hi, lo;
            split_pack(feat[2 * j], feat[2 * j + 1], hi, lo);
            AhW[tid * AW_PE + j] = hi;
            AlW[tid * AW_PE + j] = lo;
        }
    }

    float acc[2][16][4];
    const float* bias_s = (const float*)(smraw + SM_BIAS);

    // ---- three GEMM layers: L0 (chunks 0-1, AW_PE), L1 (2-9), L2 (10-17) ----
#pragma unroll 1
    for (int layer = 0; layer < 3; ++layer) {
        const int g0 = (layer == 0) ? 0 : (layer == 1) ? 2 : 10;
        const int nc = (layer == 0) ? 2 : 8;
        const int AW = (layer == 0) ? AW_PE : AW_BIG;
#pragma unroll
        for (int i = 0; i < 2; ++i)
#pragma unroll
            for (int j = 0; j < 16; ++j) {
                acc[i][j][0] = 0.f; acc[i][j][1] = 0.f;
                acc[i][j][2] = 0.f; acc[i][j][3] = 0.f;
            }
#pragma unroll 1
        for (int c = 0; c < nc; ++c) {
            const int g = g0 + c;
            asm volatile("cp.async.wait_group 0;" ::: "memory");
            __syncthreads();
            if (g + 1 < N_CHUNKS) {
                uint32_t dst = smb + SB + (((g + 1) & 1) ? CHUNK_BYTES : 0u);
                const unsigned char* src = g_wscr + (size_t)(g + 1) * CHUNK_BYTES;
                for (int s = tid; s < 2560; s += 256)
                    cp16(dst + (uint32_t)s * 16u, src + s * 16);
                asm volatile("cp.async.commit_group;" ::: "memory");
            }
            const uint32_t* Bh = (const uint32_t*)(smraw + SB + ((g & 1) ? CHUNK_BYTES : 0u));
            chunk_mma(acc, AhW, AlW, AW, Bh, Bh + 5120, c * 32, m0, n0, gq, tig);
        }
        // ---- epilogue: bias + relu + hi/lo split -> A planes (AW_BIG) ----
        const float* bs = bias_s + layer * 256;
        __syncthreads();                       // all GEMM reads of A done
#pragma unroll
        for (int i = 0; i < 2; ++i) {
            const int r = m0 + i * 16 + gq;
#pragma unroll
            for (int j = 0; j < 16; ++j) {
                const int col = n0 + j * 8 + 2 * tig;
                const float bb0 = bs[col], bb1 = bs[col + 1];
                float v0 = fmaxf(acc[i][j][0] + bb0, 0.f);
                float v1 = fmaxf(acc[i][j][1] + bb1, 0.f);
                float v2 = fmaxf(acc[i][j][2] + bb0, 0.f);
                float v3 = fmaxf(acc[i][j][3] + bb1, 0.f);
                uint32_t h0, l0, h1, l1;
                split_pack(v0, v1, h0, l0);
                split_pack(v2, v3, h1, l1);
                const int w = col >> 1;
                AhW[r * AW_BIG + w] = h0;        AlW[r * AW_BIG + w] = l0;
                AhW[(r + 8) * AW_BIG + w] = h1;  AlW[(r + 8) * AW_BIG + w] = l1;
            }
        }
        __syncthreads();
    }

    // ---- layer 3 (256 -> 4), scalar fp32: thread -> (point, 2 output cols) ----
    float* out4s  = (float*)(smraw + SM_RED);
    float* alphas = out4s + 512;
    float* rgbs   = alphas + 128;
    {
        const int p = tid >> 1;
        const int c = (tid & 1) * 2;
        const float* W3s = (const float*)(smraw + SM_W3);
        const float* b3s = (const float*)(smraw + SM_B3);
        float s0 = b3s[c], s1 = b3s[c + 1];
        const uint32_t* hr = AhW + p * AW_BIG;
        const uint32_t* lr = AlW + p * AW_BIG;
#pragma unroll 4
        for (int w = 0; w < 128; ++w) {
            uint32_t hw = hr[w], lw = lr[w];
            float x0 = bf_lo(hw) + bf_lo(lw);
            float x1 = bf_hi(hw) + bf_hi(lw);
            const float* w3a = W3s + (2 * w) * 4;
            s0 = fmaf(x0, w3a[c],     s0); s0 = fmaf(x1, w3a[4 + c],     s0);
            s1 = fmaf(x0, w3a[c + 1], s1); s1 = fmaf(x1, w3a[4 + c + 1], s1);
        }
        out4s[p * 4 + c]     = s0;
        out4s[p * 4 + c + 1] = s1;
    }
    __syncthreads();

    // ---- alpha / rgb + per-ray composite ----
    if (tid < 128) {
        const int s = tid & 63;
        float sig = fmaxf(out4s[tid * 4 + 3], 0.f);
        float delta = (nearv + step * (float)(s + 1)) - (nearv + step * (float)s);
        alphas[tid] = 1.f - expf(-sig * delta);
        rgbs[tid * 3 + 0] = 1.f / (1.f + expf(-out4s[tid * 4 + 0]));
        rgbs[tid * 3 + 1] = 1.f / (1.f + expf(-out4s[tid * 4 + 1]));
        rgbs[tid * 3 + 2] = 1.f / (1.f + expf(-out4s[tid * 4 + 2]));
    }
    __syncthreads();
    if (tid < 6) {
        const int r = tid / 3, c = tid % 3;
        float T = 1.f, a_out = 0.f;
#pragma unroll 1
        for (int s = 0; s < 64; ++s) {
            float a = alphas[r * 64 + s];
            a_out += T * a * rgbs[(r * 64 + s) * 3 + c];
            T *= (1.f - a);
        }
        out[(blockIdx.x * 2 + r) * 3 + c] = a_out;
    }
}

extern "C" void kernel_launch(void* const* d_in, const int* in_sizes, int n_in,
                              void* d_out, int out_size) {
    const float* origins = (const float*)d_in[0];
    const float* dirs    = (const float*)d_in[1];
    const float* nearp   = (const float*)d_in[2];
    const float* farp    = (const float*)d_in[3];
    const float* W0 = (const float*)d_in[4];
    const float* b0 = (const float*)d_in[5];
    const float* W1 = (const float*)d_in[6];
    const float* b1 = (const float*)d_in[7];
    const float* W2 = (const float*)d_in[8];
    const float* b2 = (const float*)d_in[9];
    const float* W3 = (const float*)d_in[10];
    const float* b3 = (const float*)d_in[11];
    float* out = (float*)d_out;

    cudaFuncSetAttribute(nerf_hmma_kernel,
                         cudaFuncAttributeMaxDynamicSharedMemorySize, SMEM_BYTES);

    nerf_prep_kernel<<<N_CHUNKS, 256>>>(W0, W1, W2);
    int rays = in_sizes[0] / 3;             // 2048
    nerf_hmma_kernel<<<rays / 2, 256, SMEM_BYTES>>>(
        origins, dirs, nearp, farp, b0, b1, b2, W3, b3, out);
}